// round 14
// baseline (speedup 1.0000x reference)
#include <cuda_runtime.h>
#include <cuda_bf16.h>
#include <cuda_fp16.h>
#include <math.h>
#include <stdint.h>

#define BB 16
#define CC 512
#define HWDIM 1024
#define NN 16384            // B*H*W
#define MM 1024
#define UQ_STRIDE (2*CC*HWDIM)          // per-batch stride of updated_query = 1048576

// output offsets (floats)
#define OFF_UQ   ((size_t)0)
#define OFF_UMEM ((size_t)BB*UQ_STRIDE)                  // 16777216
#define OFF_SQ   (OFF_UMEM + (size_t)MM*CC)              // 17301504
#define OFF_SM   (OFF_SQ + (size_t)NN*MM)                // 34078720
#define OFF_DIV  (OFF_SM + (size_t)NN*MM)                // 50855936
#define OFF_SIM  (OFF_DIV + 1)

// ---------------- scratch (static device globals; no runtime alloc) ----------------
__device__ float g_rrowsum[NN];
__device__ int   g_argm[NN];
__device__ float g_w[NN];
__device__ float g_rcolsum[MM];
__device__ float g_knacc[MM];
__device__ float g_qupd[MM*CC];       // zero-init at load; re-zeroed by k_umem each run
__device__ unsigned g_entmax_bits;
// atomic merge targets for fused score reductions
__device__ unsigned long long g_rowkey[NN];   // (float_bits(max) << 32) | ~argmax
__device__ float g_rowsumacc[NN];
__device__ unsigned g_colmaxb[MM];
__device__ float g_colsumacc[MM];
// bf16 split operands (score GEMM, 3-term)
__device__ __nv_bfloat16 g_qhi[(size_t)NN*CC];   // qr [N][C] K-major
__device__ __nv_bfloat16 g_qlo[(size_t)NN*CC];
__device__ __nv_bfloat16 g_khi[(size_t)MM*CC];   // keys [M][C]
__device__ __nv_bfloat16 g_klo[(size_t)MM*CC];
// fp16 operands (read/gram GEMMs)
__device__ __half g_kThi[(size_t)CC*MM];         // fp16(keys^T) [C][M]
__device__ __half g_vhi[(size_t)NN*MM];          // fp16(v) [N][M]
__device__ __half g_uhi[(size_t)MM*CC];          // updated_memory split
__device__ __half g_ulo[(size_t)MM*CC];

// ---------------- PTX helpers (base sm_103-legal only) ----------------
__device__ __forceinline__ uint32_t smem_u32(const void* p) {
    uint32_t a;
    asm("{ .reg .u64 t; cvta.to.shared.u64 t, %1; cvt.u32.u64 %0, t; }" : "=r"(a) : "l"(p));
    return a;
}
__device__ __forceinline__ void ldm_x4(uint32_t* r, uint32_t a) {
    asm volatile("ldmatrix.sync.aligned.m8n8.x4.shared.b16 {%0,%1,%2,%3}, [%4];"
        : "=r"(r[0]), "=r"(r[1]), "=r"(r[2]), "=r"(r[3]) : "r"(a));
}
__device__ __forceinline__ void mma_bf16(float* c, const uint32_t* a, const uint32_t* b) {
    asm volatile("mma.sync.aligned.m16n8k16.row.col.f32.bf16.bf16.f32 "
        "{%0,%1,%2,%3}, {%4,%5,%6,%7}, {%8,%9}, {%0,%1,%2,%3};"
        : "+f"(c[0]), "+f"(c[1]), "+f"(c[2]), "+f"(c[3])
        : "r"(a[0]), "r"(a[1]), "r"(a[2]), "r"(a[3]), "r"(b[0]), "r"(b[1]));
}
__device__ __forceinline__ void mma_f16(float* c, const uint32_t* a, const uint32_t* b) {
    asm volatile("mma.sync.aligned.m16n8k16.row.col.f32.f16.f16.f32 "
        "{%0,%1,%2,%3}, {%4,%5,%6,%7}, {%8,%9}, {%0,%1,%2,%3};"
        : "+f"(c[0]), "+f"(c[1]), "+f"(c[2]), "+f"(c[3])
        : "r"(a[0]), "r"(a[1]), "r"(a[2]), "r"(a[3]), "r"(b[0]), "r"(b[1]));
}
__device__ __forceinline__ void cpa16(uint32_t dst, const void* src) {
    asm volatile("cp.async.ca.shared.global [%0], [%1], 16;" :: "r"(dst), "l"(src));
}
#define CP_COMMIT asm volatile("cp.async.commit_group;" ::: "memory")
#define CP_WAIT1  asm volatile("cp.async.wait_group 1;" ::: "memory")
#define CP_WAIT0  asm volatile("cp.async.wait_group 0;" ::: "memory")

// ---------------- small kernels ----------------

__global__ void k_init(const float* __restrict__ ent, float* __restrict__ out) {
    int i = blockIdx.x * blockDim.x + threadIdx.x;   // grid covers NN
    if (i < NN) {
        g_rowkey[i] = 0ull;
        g_rowsumacc[i] = 0.f;
        atomicMax(&g_entmax_bits, __float_as_uint(ent[i])); // entropy > 0
    }
    if (i < MM) {
        g_colmaxb[i] = 0u;
        g_colsumacc[i] = 0.f;
        g_knacc[i] = 0.f;
    }
    if (i == 0) {
        out[OFF_DIV] = 0.f;
        out[OFF_SIM] = 0.f;
    }
}

// keys -> bf16 hi/lo split [M][C], fp16(keys^T) [C][M], AND per-row norm partials
__global__ void k_keys(const float* __restrict__ keys) {
    __shared__ float t[32][33];
    int m0 = blockIdx.x * 32, c0 = blockIdx.y * 32;
    int tx = threadIdx.x, ty = threadIdx.y;  // 32 x 8; warp == fixed ty
    #pragma unroll
    for (int i = 0; i < 4; i++) {
        int row = ty + i*8;
        size_t o = (size_t)(m0 + row)*CC + c0 + tx;
        float v = keys[o];
        t[row][tx] = v;
        __nv_bfloat16 hi = __float2bfloat16(v);
        g_khi[o] = hi;
        g_klo[o] = __float2bfloat16(v - __bfloat162float(hi));
        float s = v*v;
        #pragma unroll
        for (int off = 16; off > 0; off >>= 1) s += __shfl_down_sync(0xffffffffu, s, off);
        if (tx == 0) atomicAdd(&g_knacc[m0 + row], s);
    }
    __syncthreads();
    #pragma unroll
    for (int i = 0; i < 4; i++) {
        float v = t[tx][ty + i*8];        // = keys[m0+tx][c0+ty+i*8]
        g_kThi[(size_t)(c0 + ty + i*8)*MM + m0 + tx] = __float2half_rn(v);
    }
}

// ---------------- fused: load q column-block, compute norms, write qr + bf16 split ----------------
#define QPITCH 36
#define QSMEM (512*QPITCH*4 + 128)

__global__ void __launch_bounds__(256) k_qnorm(const float* __restrict__ q, float* __restrict__ out) {
    extern __shared__ float qs[];          // [512][QPITCH] + rn[32]
    float* rn = qs + 512*QPITCH;
    int b = blockIdx.y;
    int hw0 = blockIdx.x * 32;
    int tid = threadIdx.x;
    int col = tid & 31, r0 = tid >> 5;     // 8 row-groups
    const float* src = q + (size_t)b*CC*HWDIM + hw0;
    #pragma unroll 8
    for (int i = 0; i < 64; i++) {
        int row = r0 + i*8;
        qs[row*QPITCH + col] = src[(size_t)row*HWDIM + col];
    }
    __syncthreads();
    // norms: 8 warps x 4 hw; 8 lanes per hw (conflict-free: bank = 4cb + hwl)
    int w = tid >> 5, l = tid & 31;
    {
        int hwl = w*4 + (l >> 3);
        int cb = l & 7;
        float s = 0.f;
        #pragma unroll 8
        for (int k = 0; k < 64; k++) {
            float v = qs[(cb + k*8)*QPITCH + hwl];
            s += v*v;
        }
        s += __shfl_xor_sync(0xffffffffu, s, 1);
        s += __shfl_xor_sync(0xffffffffu, s, 2);
        s += __shfl_xor_sync(0xffffffffu, s, 4);
        if (cb == 0) rn[hwl] = 1.f / fmaxf(sqrtf(s), 1e-12f);
    }
    __syncthreads();
    // write fp32 qr (BCHW layout)
    float* dst = out + (size_t)b*UQ_STRIDE + hw0;
    float rcol = rn[col];
    #pragma unroll 8
    for (int i = 0; i < 64; i++) {
        int row = r0 + i*8;
        dst[(size_t)row*HWDIM + col] = qs[row*QPITCH + col] * rcol;
    }
    // transposed bf16 hi/lo [n][c]: 8 lanes over c x 4 hw per warp (conflict-free)
    {
        int hwl = w*4 + (l >> 3);
        int n = (b << 10) | (hw0 + hwl);
        float rr = rn[hwl];
        #pragma unroll 4
        for (int cb = 0; cb < 64; cb++) {
            int c = cb*8 + (l & 7);
            float v = qs[c*QPITCH + hwl] * rr;
            __nv_bfloat16 hi = __float2bfloat16(v);
            g_qhi[(size_t)n*CC + c] = hi;
            g_qlo[(size_t)n*CC + c] = __float2bfloat16(v - __bfloat162float(hi));
        }
    }
}

// ---------------- HMMA score GEMM: co-staged bf16 hi/lo, ring-3, one barrier per stage ----------------
// A/B buffer row: [hi 64B | lo 64B | pad 16B] = 144B
#define SBUF 18432      // 128 * 144
#define DSMEM_S (6*SBUF)  // 3 A + 3 B = 110592

__global__ void __launch_bounds__(256, 2) k_score_mma() {
    extern __shared__ __align__(16) char dsm[];
    int tid = threadIdx.x, l = tid & 31, w = tid >> 5;
    int wr = w >> 2, wc = w & 3;
    int m0 = blockIdx.x * 128, n0 = blockIdx.y * 128;
    uint32_t as0 = smem_u32(dsm);
    uint32_t bs0 = as0 + 3*SBUF;

    float acc[4][4][4];
    #pragma unroll
    for (int i = 0; i < 4; i++)
        #pragma unroll
        for (int j = 0; j < 4; j++)
            #pragma unroll
            for (int k = 0; k < 4; k++) acc[i][j][k] = 0.f;

    auto stage = [&](int s, int buf) {
        #pragma unroll
        for (int t = 0; t < 4; t++) {
            int idx = tid + t*256;
            int r = idx >> 3, c = idx & 7;
            const char* srcA = (c < 4)
                ? (const char*)g_qhi + (size_t)(n0 + r)*1024 + s*64 + c*16
                : (const char*)g_qlo + (size_t)(n0 + r)*1024 + s*64 + (c-4)*16;
            cpa16(as0 + buf*SBUF + r*144 + c*16, srcA);
            const char* srcB = (c < 4)
                ? (const char*)g_khi + (size_t)(m0 + r)*1024 + s*64 + c*16
                : (const char*)g_klo + (size_t)(m0 + r)*1024 + s*64 + (c-4)*16;
            cpa16(bs0 + buf*SBUF + r*144 + c*16, srcB);
        }
        CP_COMMIT;
    };

    uint32_t a_off = (uint32_t)((l & 15)*144 + (l >> 4)*16);
    uint32_t b_off = (uint32_t)(((((l >> 4) & 1)*8) + (l & 7))*144 + ((l >> 3) & 1)*16);

    stage(0, 0); stage(1, 1);
    const int NIT = 16;
    for (int it = 0; it < NIT; it++) {
        int buf = it % 3;
        if (it < NIT - 1) CP_WAIT1; else CP_WAIT0;
        __syncthreads();
        if (it + 2 < NIT) stage(it + 2, (it + 2) % 3);
        #pragma unroll
        for (int h = 0; h < 2; h++) {
            uint32_t afr[4][4], b0f[2][4], b1f[2][4];
            // A-hi, B-hi
            #pragma unroll
            for (int fi = 0; fi < 4; fi++)
                ldm_x4(afr[fi], as0 + buf*SBUF + (wr*64 + fi*16)*144 + h*32 + a_off);
            #pragma unroll
            for (int jp = 0; jp < 2; jp++)
                ldm_x4(b0f[jp], bs0 + buf*SBUF + (wc*32 + jp*16)*144 + h*32 + b_off);
            #pragma unroll
            for (int fi = 0; fi < 4; fi++)
                #pragma unroll
                for (int fj = 0; fj < 4; fj++)
                    mma_bf16(acc[fi][fj], afr[fi], &b0f[fj >> 1][(fj & 1)*2]);   // hi*hi
            // B-lo (A-hi still live)
            #pragma unroll
            for (int jp = 0; jp < 2; jp++)
                ldm_x4(b1f[jp], bs0 + buf*SBUF + (wc*32 + jp*16)*144 + 64 + h*32 + b_off);
            #pragma unroll
            for (int fi = 0; fi < 4; fi++)
                #pragma unroll
                for (int fj = 0; fj < 4; fj++)
                    mma_bf16(acc[fi][fj], afr[fi], &b1f[fj >> 1][(fj & 1)*2]);   // hi*lo
            // A-lo (reuse B-hi)
            #pragma unroll
            for (int fi = 0; fi < 4; fi++)
                ldm_x4(afr[fi], as0 + buf*SBUF + (wr*64 + fi*16)*144 + 64 + h*32 + a_off);
            #pragma unroll
            for (int fi = 0; fi < 4; fi++)
                #pragma unroll
                for (int fj = 0; fj < 4; fj++)
                    mma_bf16(acc[fi][fj], afr[fi], &b0f[fj >> 1][(fj & 1)*2]);   // lo*hi
        }
    }

    // ---- epilogue: exp, fp16 v, fused row/col reductions ----
    int g = l >> 2, t2 = (l & 3)*2;
    float rsum[8], rmaxv[8]; int rargm[8];
    float csum[8], cmaxv[8];
    #pragma unroll
    for (int i = 0; i < 8; i++) { rsum[i]=0.f; rmaxv[i]=0.f; rargm[i]=0; csum[i]=0.f; cmaxv[i]=0.f; }

    #pragma unroll
    for (int fi = 0; fi < 4; fi++) {
        int r0 = n0 + wr*64 + fi*16 + g;
        #pragma unroll
        for (int fj = 0; fj < 4; fj++) {
            int c = m0 + wc*32 + fj*8 + t2;
            float* p = acc[fi][fj];
            #pragma unroll
            for (int hh = 0; hh < 2; hh++) {
                int r = r0 + hh*8;
                int ridx = fi*2 + hh;
                float e0 = __expf(p[hh*2 + 0]);
                float e1 = __expf(p[hh*2 + 1]);
                size_t o = (size_t)r*MM + c;
                __half2 hv; hv.x = __float2half_rn(e0); hv.y = __float2half_rn(e1);
                *(__half2*)(g_vhi + o) = hv;
                rsum[ridx] += e0 + e1;
                if (e0 > rmaxv[ridx]) { rmaxv[ridx] = e0; rargm[ridx] = c; }
                if (e1 > rmaxv[ridx]) { rmaxv[ridx] = e1; rargm[ridx] = c + 1; }
                int cidx = fj*2;
                csum[cidx]   += e0; cmaxv[cidx]   = fmaxf(cmaxv[cidx],   e0);
                csum[cidx+1] += e1; cmaxv[cidx+1] = fmaxf(cmaxv[cidx+1], e1);
            }
        }
    }
    // row reduce across lanes sharing the row (xor 1,2 within lane quad)
    #pragma unroll
    for (int o = 1; o <= 2; o <<= 1) {
        #pragma unroll
        for (int i = 0; i < 8; i++) {
            float os = __shfl_xor_sync(0xffffffffu, rsum[i], o);
            float om = __shfl_xor_sync(0xffffffffu, rmaxv[i], o);
            int   oa = __shfl_xor_sync(0xffffffffu, rargm[i], o);
            rsum[i] += os;
            if (om > rmaxv[i] || (om == rmaxv[i] && oa < rargm[i])) { rmaxv[i] = om; rargm[i] = oa; }
        }
    }
    // col reduce across lanes sharing the col (xor 4,8,16)
    #pragma unroll
    for (int o = 4; o <= 16; o <<= 1) {
        #pragma unroll
        for (int i = 0; i < 8; i++) {
            csum[i]  += __shfl_xor_sync(0xffffffffu, csum[i], o);
            cmaxv[i]  = fmaxf(cmaxv[i], __shfl_xor_sync(0xffffffffu, cmaxv[i], o));
        }
    }
    // smem merge (reuse pipeline smem)
    float* s_rs = (float*)dsm;
    float* s_rm = s_rs + 128;
    int*   s_ra = (int*)(s_rm + 128);
    float* s_cs = (float*)(s_ra + 128);
    float* s_cm = s_cs + 128;
    __syncthreads();
    for (int ws = 0; ws < 4; ws++) {          // stage over wc; wr rows disjoint
        if (wc == ws && (l & 3) == 0) {
            #pragma unroll
            for (int i = 0; i < 8; i++) {
                int r = wr*64 + (i >> 1)*16 + (i & 1)*8 + g;
                if (ws == 0) { s_rs[r] = rsum[i]; s_rm[r] = rmaxv[i]; s_ra[r] = rargm[i]; }
                else {
                    s_rs[r] += rsum[i];
                    if (rmaxv[i] > s_rm[r] || (rmaxv[i] == s_rm[r] && rargm[i] < s_ra[r])) {
                        s_rm[r] = rmaxv[i]; s_ra[r] = rargm[i];
                    }
                }
            }
        }
        __syncthreads();
    }
    for (int ws = 0; ws < 2; ws++) {          // stage over wr; wc cols disjoint
        if (wr == ws && l < 4) {
            #pragma unroll
            for (int i = 0; i < 8; i++) {
                int cl = wc*32 + (i >> 1)*8 + t2 + (i & 1);
                if (ws == 0) { s_cs[cl] = csum[i]; s_cm[cl] = cmaxv[i]; }
                else { s_cs[cl] += csum[i]; s_cm[cl] = fmaxf(s_cm[cl], cmaxv[i]); }
            }
        }
        __syncthreads();
    }
    if (tid < 128) {
        int n = n0 + tid;
        atomicAdd(&g_rowsumacc[n], s_rs[tid]);
        unsigned long long key =
            ((unsigned long long)__float_as_uint(s_rm[tid]) << 32) | (unsigned)(~(unsigned)s_ra[tid]);
        atomicMax(&g_rowkey[n], key);
        int m = m0 + tid;
        atomicAdd(&g_colsumacc[m], s_cs[tid]);
        atomicMax(&g_colmaxb[m], __float_as_uint(s_cm[tid]));
    }
}

// ---------------- finalize reductions + w[n] + similarity loss (merged fin+wsim) ----------------
__global__ void k_finw(const float* __restrict__ ent, float* __restrict__ out) {
    int n = blockIdx.x * blockDim.x + threadIdx.x;
    float local = 0.f;
    if (n < NN) {
        unsigned long long key = g_rowkey[n];
        float rmax = __uint_as_float((unsigned)(key >> 32));
        int g = (int)(~(unsigned)key);
        g_argm[n] = g;
        g_rrowsum[n] = 1.f / g_rowsumacc[n];
        float en = ent[n];
        float entmax = __uint_as_float(g_entmax_bits);
        float colmax = __uint_as_float(g_colmaxb[g]);
        g_w[n] = (rmax / colmax) * (en / entmax);
        float kn = sqrtf(g_knacc[g]);
        float cosv = logf(rmax) / fmaxf(kn, 1e-8f);   // ||qr|| == 1
        local = (1.f - cosv) * en;
    }
    if (n < MM) g_rcolsum[n] = 1.f / g_colsumacc[n];
    __shared__ float red[256];
    red[threadIdx.x] = local;
    __syncthreads();
    for (int o = 128; o > 0; o >>= 1) {
        if (threadIdx.x < o) red[threadIdx.x] += red[threadIdx.x + o];
        __syncthreads();
    }
    if (threadIdx.x == 0) atomicAdd(out + OFF_SIM, red[0]);
}

// ---------------- HMMA read GEMM (fp16, 1-term, 128x128) + fused sq/sm write ----------------
#define RBUF 10240      // 128 * 80
#define DSMEM_R (6*RBUF)   // 3 A + 3 B = 61440, ring-3

__global__ void __launch_bounds__(256, 2) k_read_mma(float* __restrict__ out) {
    extern __shared__ __align__(16) char dsm[];
    int tid = threadIdx.x, l = tid & 31, w = tid >> 5;
    int wr = w >> 2, wc = w & 3;
    int c0 = blockIdx.x * 128, n0 = blockIdx.y * 128;
    uint32_t as0 = smem_u32(dsm);
    uint32_t bs0 = as0 + 3*RBUF;

    float acc[4][4][4];
    #pragma unroll
    for (int i = 0; i < 4; i++)
        #pragma unroll
        for (int j = 0; j < 4; j++)
            #pragma unroll
            for (int k = 0; k < 4; k++) acc[i][j][k] = 0.f;

    auto stage = [&](int s, int buf) {
        #pragma unroll
        for (int t = 0; t < 2; t++) {
            int idx = tid + t*256;
            int r = idx >> 2, c = idx & 3;
            cpa16(as0 + buf*RBUF + r*80 + c*16,
                  (const char*)g_vhi + (size_t)(n0 + r)*2048 + s*64 + c*16);
            cpa16(bs0 + buf*RBUF + r*80 + c*16,
                  (const char*)g_kThi + (size_t)(c0 + r)*2048 + s*64 + c*16);
        }
        CP_COMMIT;
    };

    uint32_t a_off = (uint32_t)((l & 15)*80 + (l >> 4)*16);
    uint32_t b_off = (uint32_t)(((((l >> 4) & 1)*8) + (l & 7))*80 + ((l >> 3) & 1)*16);

    stage(0, 0); stage(1, 1);
    const int NIT = 32;               // 1024 m / 32 per stage
    for (int it = 0; it < NIT; it++) {
        int buf = it % 3;
        if (it < NIT - 1) CP_WAIT1; else CP_WAIT0;
        __syncthreads();
        if (it + 2 < NIT) stage(it + 2, (it + 2) % 3);
        #pragma unroll
        for (int h = 0; h < 2; h++) {
            uint32_t a[4][4], bfr[2][4];
            #pragma unroll
            for (int jp = 0; jp < 2; jp++)
                ldm_x4(bfr[jp], bs0 + buf*RBUF + (wc*32 + jp*16)*80 + h*32 + b_off);
            #pragma unroll
            for (int fi = 0; fi < 4; fi++)
                ldm_x4(a[fi], as0 + buf*RBUF + (wr*64 + fi*16)*80 + h*32 + a_off);
            #pragma unroll
            for (int fi = 0; fi < 4; fi++)
                #pragma unroll
                for (int fj = 0; fj < 4; fj++)
                    mma_f16(acc[fi][fj], a[fi], &bfr[fj >> 1][(fj & 1)*2]);
        }
        // fused sq/sm write: each c0-block writes its quarter of the 128 n-rows
        if (tid < 128) {
            int r = (blockIdx.x << 5) + (tid >> 2);
            int c = tid & 3;
            const __half2* hp = (const __half2*)(dsm + buf*RBUF + r*80 + c*16);
            int n = n0 + r;
            int m = it*32 + c*8;
            float rr = g_rrowsum[n];
            float4 rc0 = *(const float4*)(g_rcolsum + m);
            float4 rc1 = *(const float4*)(g_rcolsum + m + 4);
            float vv[8];
            #pragma unroll
            for (int j = 0; j < 4; j++) {
                float2 hf = __half22float2(hp[j]);
                vv[j*2]   = hf.x;
                vv[j*2+1] = hf.y;
            }
            size_t o = (size_t)n*MM + m;
            float4 sq0 = make_float4(vv[0]*rc0.x, vv[1]*rc0.y, vv[2]*rc0.z, vv[3]*rc0.w);
            float4 sq1 = make_float4(vv[4]*rc1.x, vv[5]*rc1.y, vv[6]*rc1.z, vv[7]*rc1.w);
            *(float4*)(out + OFF_SQ + o)     = sq0;
            *(float4*)(out + OFF_SQ + o + 4) = sq1;
            float4 sm0 = make_float4(vv[0]*rr, vv[1]*rr, vv[2]*rr, vv[3]*rr);
            float4 sm1 = make_float4(vv[4]*rr, vv[5]*rr, vv[6]*rr, vv[7]*rr);
            *(float4*)(out + OFF_SM + o)     = sm0;
            *(float4*)(out + OFF_SM + o + 4) = sm1;
        }
    }

    // epilogue: scale by rrowsum, write BCHW channels [C, 2C)
    int g = l >> 2, t2 = (l & 3)*2;
    int b = n0 >> 10;
    int hwb = n0 & 1023;
    float* obase = out + (size_t)b*UQ_STRIDE;
    #pragma unroll
    for (int fi = 0; fi < 4; fi++) {
        int rl0 = wr*64 + fi*16 + g;
        float rs0 = g_rrowsum[n0 + rl0];
        float rs1 = g_rrowsum[n0 + rl0 + 8];
        #pragma unroll
        for (int fj = 0; fj < 4; fj++) {
            int c = c0 + wc*32 + fj*8 + t2;
            float* p = acc[fi][fj];
            size_t a0 = (size_t)(CC + c)*HWDIM + hwb + rl0;
            obase[a0]              = p[0] * rs0;
            obase[a0 + HWDIM]      = p[1] * rs0;
            obase[a0 + 8]          = p[2] * rs1;
            obase[a0 + HWDIM + 8]  = p[3] * rs1;
        }
    }
}

// ---------------- HMMA gram GEMM (fp16, 2-term): diversity(updated_memory) ----------------
#define GBUF 10240      // 128 rows * 80B
#define DSMEM_G (8*GBUF)

__global__ void __launch_bounds__(256, 2) k_gram_mma(float* __restrict__ out) {
    extern __shared__ __align__(16) char dsm[];
    __shared__ float red[256];
    int tid = threadIdx.x, l = tid & 31, w = tid >> 5;
    int wr = w >> 2, wc = w & 3;
    int j0 = blockIdx.x * 128, i0 = blockIdx.y * 128;
    const __half* Ap[2] = {g_uhi, g_ulo};
    uint32_t as0 = smem_u32(dsm);
    uint32_t bs0 = as0 + 4*GBUF;

    float acc[4][4][4];
    #pragma unroll
    for (int i = 0; i < 4; i++)
        #pragma unroll
        for (int j = 0; j < 4; j++)
            #pragma unroll
            for (int k = 0; k < 4; k++) acc[i][j][k] = 0.f;

    int row2 = tid >> 2, ch = tid & 3;
    auto stage = [&](int it, int buf) {
        int seg = it >> 4;
        int k0b = (it & 15) * 64;
        const char* Ab = (const char*)Ap[seg] + (size_t)i0*1024 + k0b;
        const char* Bb = (const char*)g_uhi + (size_t)j0*1024 + k0b;
        #pragma unroll
        for (int t = 0; t < 2; t++) {
            int r = row2 + t*64;
            cpa16(as0 + buf*GBUF + r*80 + ch*16, Ab + (size_t)r*1024 + ch*16);
            cpa16(bs0 + buf*GBUF + r*80 + ch*16, Bb + (size_t)r*1024 + ch*16);
        }
        CP_COMMIT;
    };

    uint32_t a_off = (uint32_t)((l & 15)*80 + (l >> 4)*16);
    uint32_t b_off = (uint32_t)(((((l >> 4) & 1)*8) + (l & 7))*80 + ((l >> 3) & 1)*16);

    stage(0, 0); stage(1, 1);
    const int NIT = 32;
    for (int it = 0; it < NIT; it++) {
        int buf = it & 3;
        if (it < NIT - 1) CP_WAIT1; else CP_WAIT0;
        __syncthreads();
        if (it + 2 < NIT) stage(it + 2, (it + 2) & 3);
        #pragma unroll
        for (int h = 0; h < 2; h++) {
            uint32_t a[4][4];
            #pragma unroll
            for (int fi = 0; fi < 4; fi++)
                ldm_x4(a[fi], as0 + buf*GBUF + (wr*64 + fi*16)*80 + h*32 + a_off);
            uint32_t bfr[2][4];
            #pragma unroll
            for (int jp = 0; jp < 2; jp++)
                ldm_x4(bfr[jp], bs0 + buf*GBUF + (wc*32 + jp*16)*80 + h*32 + b_off);
            #pragma unroll
            for (int fi = 0; fi < 4; fi++)
                #pragma unroll
                for (int fj = 0; fj < 4; fj++)
                    mma_f16(acc[fi][fj], a[fi], &bfr[fj >> 1][(fj & 1)*2]);
        }
    }

    int g = l >> 2, t2 = (l & 3)*2;
    float local = 0.f;
    #pragma unroll
    for (int fi = 0; fi < 4; fi++) {
        int r0 = i0 + wr*64 + fi*16 + g;
        #pragma unroll
        for (int fj = 0; fj < 4; fj++) {
            int c = j0 + wc*32 + fj*8 + t2;
            float* p = acc[fi][fj];
            if (r0 != c)         local += p[0]*p[0];
            if (r0 != c + 1)     local += p[1]*p[1];
            if (r0 + 8 != c)     local += p[2]*p[2];
            if (r0 + 8 != c + 1) local += p[3]*p[3];
        }
    }
    red[tid] = local;
    __syncthreads();
    for (int o = 128; o > 0; o >>= 1) {
        if (tid < o) red[tid] += red[tid + o];
        __syncthreads();
    }
    if (tid == 0) atomicAdd(out + OFF_DIV, red[0] * (1.f / (float)(MM*MM - MM)));
}

// ---------------- segment-sum: qupd[g[n], c] += w[n]*qr[n,c] ----------------
__global__ void k_segsum(const float* __restrict__ out) {
    int idx = blockIdx.x * blockDim.x + threadIdx.x;
    if (idx >= BB*CC*HWDIM) return;
    int b = idx >> 19;
    int rem = idx & ((CC*HWDIM) - 1);
    int c = rem >> 10;
    int hw = idx & 1023;
    int n = (b << 10) | hw;
    float val = out[(size_t)b*UQ_STRIDE + rem];           // qr in BCHW layout
    atomicAdd(&g_qupd[(size_t)g_argm[n]*CC + c], g_w[n] * val);
}

// ---------------- updated memory: l2norm(qupd + keys), emit fp32 + fp16 split; re-zero qupd ----------------
__global__ void k_umem(const float* __restrict__ keys, float* __restrict__ out) {
    int m = blockIdx.x;
    int t = threadIdx.x;   // 128
    float vals[4]; float s = 0.f;
    #pragma unroll
    for (int i = 0; i < 4; i++) {
        int c = t + i*128;
        vals[i] = g_qupd[(size_t)m*CC + c] + keys[(size_t)m*CC + c];
        g_qupd[(size_t)m*CC + c] = 0.f;   // deferred zero for next graph replay
        s += vals[i]*vals[i];
    }
    for (int o = 16; o > 0; o >>= 1) s += __shfl_down_sync(0xffffffffu, s, o);
    __shared__ float red[4]; __shared__ float srn;
    if ((t & 31) == 0) red[t >> 5] = s;
    __syncthreads();
    if (t == 0) srn = 1.f / fmaxf(sqrtf(red[0]+red[1]+red[2]+red[3]), 1e-12f);
    __syncthreads();
    float rn = srn;
    #pragma unroll
    for (int i = 0; i < 4; i++) {
        int c = t + i*128;
        float u = vals[i] * rn;
        out[OFF_UMEM + (size_t)m*CC + c] = u;
        __half hi = __float2half_rn(u);
        g_uhi[(size_t)m*CC + c] = hi;
        g_ulo[(size_t)m*CC + c] = __float2half_rn(u - __half2float(hi));
    }
}

// ---------------- launch ----------------
extern "C" void kernel_launch(void* const* d_in, const int* in_sizes, int n_in,
                              void* d_out, int out_size) {
    const float* q    = (const float*)d_in[0];
    const float* keys = (const float*)d_in[1];
    const float* ent  = (const float*)d_in[2];
    float* out = (float*)d_out;

    cudaFuncSetAttribute(k_qnorm,     cudaFuncAttributeMaxDynamicSharedMemorySize, QSMEM);
    cudaFuncSetAttribute(k_score_mma, cudaFuncAttributeMaxDynamicSharedMemorySize, DSMEM_S);
    cudaFuncSetAttribute(k_read_mma,  cudaFuncAttributeMaxDynamicSharedMemorySize, DSMEM_R);
    cudaFuncSetAttribute(k_gram_mma,  cudaFuncAttributeMaxDynamicSharedMemorySize, DSMEM_G);

    k_init<<<NN/256, 256>>>(ent, out);
    k_keys<<<dim3(MM/32, CC/32), dim3(32, 8)>>>(keys);
    k_qnorm<<<dim3(HWDIM/32, BB), 256, QSMEM>>>(q, out);
    k_score_mma<<<dim3(MM/128, NN/128), 256, DSMEM_S>>>();
    k_finw<<<NN/256, 256>>>(ent, out);
    k_segsum<<<(BB*CC*HWDIM)/256, 256>>>(out);
    k_umem<<<MM, 128>>>(keys, out);
    k_gram_mma<<<dim3(MM/128, MM/128), 256, DSMEM_G>>>(out);
    k_read_mma<<<dim3(CC/128, NN/128), 256, DSMEM_R>>>(out);
}

// round 15
// speedup vs baseline: 1.5019x; 1.5019x over previous
#include <cuda_runtime.h>
#include <cuda_bf16.h>
#include <cuda_fp16.h>
#include <math.h>
#include <stdint.h>

#define BB 16
#define CC 512
#define HWDIM 1024
#define NN 16384            // B*H*W
#define MM 1024
#define UQ_STRIDE (2*CC*HWDIM)          // per-batch stride of updated_query = 1048576

// output offsets (floats)
#define OFF_UQ   ((size_t)0)
#define OFF_UMEM ((size_t)BB*UQ_STRIDE)                  // 16777216
#define OFF_SQ   (OFF_UMEM + (size_t)MM*CC)              // 17301504
#define OFF_SM   (OFF_SQ + (size_t)NN*MM)                // 34078720
#define OFF_DIV  (OFF_SM + (size_t)NN*MM)                // 50855936
#define OFF_SIM  (OFF_DIV + 1)

// ---------------- scratch (static device globals; no runtime alloc) ----------------
__device__ float g_rrowsum[NN];
__device__ int   g_argm[NN];
__device__ float g_w[NN];
__device__ float g_rcolsum[MM];
__device__ float g_knacc[MM];
__device__ float g_qupd[MM*CC];       // zero-init at load; re-zeroed by k_umem each run
__device__ unsigned g_entmax_bits;
// atomic merge targets for fused score reductions
__device__ unsigned long long g_rowkey[NN];   // (float_bits(max) << 32) | ~argmax
__device__ float g_rowsumacc[NN];
__device__ unsigned g_colmaxb[MM];
__device__ float g_colsumacc[MM];
// bf16 split operands (score GEMM, 3-term)
__device__ __nv_bfloat16 g_qhi[(size_t)NN*CC];   // qr [N][C] K-major
__device__ __nv_bfloat16 g_qlo[(size_t)NN*CC];
__device__ __nv_bfloat16 g_khi[(size_t)MM*CC];   // keys [M][C]
__device__ __nv_bfloat16 g_klo[(size_t)MM*CC];
// fp16 operands (read/gram GEMMs)
__device__ __half g_kThi[(size_t)CC*MM];         // fp16(keys^T) [C][M]
__device__ __half g_vhi[(size_t)NN*MM];          // fp16(v) [N][M]
__device__ __half g_uhi[(size_t)MM*CC];          // updated_memory split
__device__ __half g_ulo[(size_t)MM*CC];

// ---------------- PTX helpers (base sm_103-legal only) ----------------
__device__ __forceinline__ uint32_t smem_u32(const void* p) {
    uint32_t a;
    asm("{ .reg .u64 t; cvta.to.shared.u64 t, %1; cvt.u32.u64 %0, t; }" : "=r"(a) : "l"(p));
    return a;
}
__device__ __forceinline__ void ldm_x4(uint32_t* r, uint32_t a) {
    asm volatile("ldmatrix.sync.aligned.m8n8.x4.shared.b16 {%0,%1,%2,%3}, [%4];"
        : "=r"(r[0]), "=r"(r[1]), "=r"(r[2]), "=r"(r[3]) : "r"(a));
}
__device__ __forceinline__ void mma_bf16(float* c, const uint32_t* a, const uint32_t* b) {
    asm volatile("mma.sync.aligned.m16n8k16.row.col.f32.bf16.bf16.f32 "
        "{%0,%1,%2,%3}, {%4,%5,%6,%7}, {%8,%9}, {%0,%1,%2,%3};"
        : "+f"(c[0]), "+f"(c[1]), "+f"(c[2]), "+f"(c[3])
        : "r"(a[0]), "r"(a[1]), "r"(a[2]), "r"(a[3]), "r"(b[0]), "r"(b[1]));
}
__device__ __forceinline__ void mma_f16(float* c, const uint32_t* a, const uint32_t* b) {
    asm volatile("mma.sync.aligned.m16n8k16.row.col.f32.f16.f16.f32 "
        "{%0,%1,%2,%3}, {%4,%5,%6,%7}, {%8,%9}, {%0,%1,%2,%3};"
        : "+f"(c[0]), "+f"(c[1]), "+f"(c[2]), "+f"(c[3])
        : "r"(a[0]), "r"(a[1]), "r"(a[2]), "r"(a[3]), "r"(b[0]), "r"(b[1]));
}
__device__ __forceinline__ void cpa16(uint32_t dst, const void* src) {
    asm volatile("cp.async.ca.shared.global [%0], [%1], 16;" :: "r"(dst), "l"(src));
}
#define CP_COMMIT asm volatile("cp.async.commit_group;" ::: "memory")
#define CP_WAIT1  asm volatile("cp.async.wait_group 1;" ::: "memory")
#define CP_WAIT0  asm volatile("cp.async.wait_group 0;" ::: "memory")

// ---------------- small kernels ----------------

__global__ void k_init(const float* __restrict__ ent, float* __restrict__ out) {
    int i = blockIdx.x * blockDim.x + threadIdx.x;   // grid covers NN
    if (i < NN) {
        g_rowkey[i] = 0ull;
        g_rowsumacc[i] = 0.f;
        atomicMax(&g_entmax_bits, __float_as_uint(ent[i])); // entropy > 0
    }
    if (i < MM) {
        g_colmaxb[i] = 0u;
        g_colsumacc[i] = 0.f;
        g_knacc[i] = 0.f;
    }
    if (i == 0) {
        out[OFF_DIV] = 0.f;
        out[OFF_SIM] = 0.f;
    }
}

// keys -> bf16 hi/lo split [M][C], fp16(keys^T) [C][M], AND per-row norm partials
__global__ void k_keys(const float* __restrict__ keys) {
    __shared__ float t[32][33];
    int m0 = blockIdx.x * 32, c0 = blockIdx.y * 32;
    int tx = threadIdx.x, ty = threadIdx.y;  // 32 x 8; warp == fixed ty
    #pragma unroll
    for (int i = 0; i < 4; i++) {
        int row = ty + i*8;
        size_t o = (size_t)(m0 + row)*CC + c0 + tx;
        float v = keys[o];
        t[row][tx] = v;
        __nv_bfloat16 hi = __float2bfloat16(v);
        g_khi[o] = hi;
        g_klo[o] = __float2bfloat16(v - __bfloat162float(hi));
        float s = v*v;
        #pragma unroll
        for (int off = 16; off > 0; off >>= 1) s += __shfl_down_sync(0xffffffffu, s, off);
        if (tx == 0) atomicAdd(&g_knacc[m0 + row], s);
    }
    __syncthreads();
    #pragma unroll
    for (int i = 0; i < 4; i++) {
        float v = t[tx][ty + i*8];        // = keys[m0+tx][c0+ty+i*8]
        g_kThi[(size_t)(c0 + ty + i*8)*MM + m0 + tx] = __float2half_rn(v);
    }
}

// ---------------- fused: load q column-block, compute norms, write qr + bf16 split ----------------
#define QPITCH 36
#define QSMEM (512*QPITCH*4 + 128)

__global__ void __launch_bounds__(256) k_qnorm(const float* __restrict__ q, float* __restrict__ out) {
    extern __shared__ float qs[];          // [512][QPITCH] + rn[32]
    float* rn = qs + 512*QPITCH;
    int b = blockIdx.y;
    int hw0 = blockIdx.x * 32;
    int tid = threadIdx.x;
    int col = tid & 31, r0 = tid >> 5;     // 8 row-groups
    const float* src = q + (size_t)b*CC*HWDIM + hw0;
    #pragma unroll 8
    for (int i = 0; i < 64; i++) {
        int row = r0 + i*8;
        qs[row*QPITCH + col] = src[(size_t)row*HWDIM + col];
    }
    __syncthreads();
    // norms: 8 warps x 4 hw; 8 lanes per hw (conflict-free: bank = 4cb + hwl)
    int w = tid >> 5, l = tid & 31;
    {
        int hwl = w*4 + (l >> 3);
        int cb = l & 7;
        float s = 0.f;
        #pragma unroll 8
        for (int k = 0; k < 64; k++) {
            float v = qs[(cb + k*8)*QPITCH + hwl];
            s += v*v;
        }
        s += __shfl_xor_sync(0xffffffffu, s, 1);
        s += __shfl_xor_sync(0xffffffffu, s, 2);
        s += __shfl_xor_sync(0xffffffffu, s, 4);
        if (cb == 0) rn[hwl] = 1.f / fmaxf(sqrtf(s), 1e-12f);
    }
    __syncthreads();
    // write fp32 qr (BCHW layout)
    float* dst = out + (size_t)b*UQ_STRIDE + hw0;
    float rcol = rn[col];
    #pragma unroll 8
    for (int i = 0; i < 64; i++) {
        int row = r0 + i*8;
        dst[(size_t)row*HWDIM + col] = qs[row*QPITCH + col] * rcol;
    }
    // transposed bf16 hi/lo [n][c]: 8 lanes over c x 4 hw per warp (conflict-free)
    {
        int hwl = w*4 + (l >> 3);
        int n = (b << 10) | (hw0 + hwl);
        float rr = rn[hwl];
        #pragma unroll 4
        for (int cb = 0; cb < 64; cb++) {
            int c = cb*8 + (l & 7);
            float v = qs[c*QPITCH + hwl] * rr;
            __nv_bfloat16 hi = __float2bfloat16(v);
            g_qhi[(size_t)n*CC + c] = hi;
            g_qlo[(size_t)n*CC + c] = __float2bfloat16(v - __bfloat162float(hi));
        }
    }
}

// ---------------- HMMA score GEMM: co-staged bf16 hi/lo, ring-2, prefetch AFTER consume ----------------
// A/B buffer row: [hi 64B | lo 64B | pad 16B] = 144B
#define SBUF 18432      // 128 * 144
#define DSMEM_S (4*SBUF)  // 2 A + 2 B = 73728

__global__ void __launch_bounds__(256, 2) k_score_mma() {
    extern __shared__ __align__(16) char dsm[];
    int tid = threadIdx.x, l = tid & 31, w = tid >> 5;
    int wr = w >> 2, wc = w & 3;
    int m0 = blockIdx.x * 128, n0 = blockIdx.y * 128;
    uint32_t as0 = smem_u32(dsm);
    uint32_t bs0 = as0 + 2*SBUF;

    float acc[4][4][4];
    #pragma unroll
    for (int i = 0; i < 4; i++)
        #pragma unroll
        for (int j = 0; j < 4; j++)
            #pragma unroll
            for (int k = 0; k < 4; k++) acc[i][j][k] = 0.f;

    auto stage = [&](int s, int buf) {
        #pragma unroll
        for (int t = 0; t < 4; t++) {
            int idx = tid + t*256;
            int r = idx >> 3, c = idx & 7;
            const char* srcA = (c < 4)
                ? (const char*)g_qhi + (size_t)(n0 + r)*1024 + s*64 + c*16
                : (const char*)g_qlo + (size_t)(n0 + r)*1024 + s*64 + (c-4)*16;
            cpa16(as0 + buf*SBUF + r*144 + c*16, srcA);
            const char* srcB = (c < 4)
                ? (const char*)g_khi + (size_t)(m0 + r)*1024 + s*64 + c*16
                : (const char*)g_klo + (size_t)(m0 + r)*1024 + s*64 + (c-4)*16;
            cpa16(bs0 + buf*SBUF + r*144 + c*16, srcB);
        }
        CP_COMMIT;
    };

    uint32_t a_off = (uint32_t)((l & 15)*144 + (l >> 4)*16);
    uint32_t b_off = (uint32_t)(((((l >> 4) & 1)*8) + (l & 7))*144 + ((l >> 3) & 1)*16);

    stage(0, 0); stage(1, 1);
    const int NIT = 16;
    for (int it = 0; it < NIT; it++) {
        int buf = it & 1;
        if (it < NIT - 1) CP_WAIT1; else CP_WAIT0;
        __syncthreads();
        #pragma unroll
        for (int h = 0; h < 2; h++) {
            uint32_t afr[4][4], b0f[2][4], b1f[2][4];
            // A-hi, B-hi
            #pragma unroll
            for (int fi = 0; fi < 4; fi++)
                ldm_x4(afr[fi], as0 + buf*SBUF + (wr*64 + fi*16)*144 + h*32 + a_off);
            #pragma unroll
            for (int jp = 0; jp < 2; jp++)
                ldm_x4(b0f[jp], bs0 + buf*SBUF + (wc*32 + jp*16)*144 + h*32 + b_off);
            #pragma unroll
            for (int fi = 0; fi < 4; fi++)
                #pragma unroll
                for (int fj = 0; fj < 4; fj++)
                    mma_bf16(acc[fi][fj], afr[fi], &b0f[fj >> 1][(fj & 1)*2]);   // hi*hi
            // B-lo (A-hi still live)
            #pragma unroll
            for (int jp = 0; jp < 2; jp++)
                ldm_x4(b1f[jp], bs0 + buf*SBUF + (wc*32 + jp*16)*144 + 64 + h*32 + b_off);
            #pragma unroll
            for (int fi = 0; fi < 4; fi++)
                #pragma unroll
                for (int fj = 0; fj < 4; fj++)
                    mma_bf16(acc[fi][fj], afr[fi], &b1f[fj >> 1][(fj & 1)*2]);   // hi*lo
            // A-lo (reuse B-hi)
            #pragma unroll
            for (int fi = 0; fi < 4; fi++)
                ldm_x4(afr[fi], as0 + buf*SBUF + (wr*64 + fi*16)*144 + 64 + h*32 + a_off);
            #pragma unroll
            for (int fi = 0; fi < 4; fi++)
                #pragma unroll
                for (int fj = 0; fj < 4; fj++)
                    mma_bf16(acc[fi][fj], afr[fi], &b0f[fj >> 1][(fj & 1)*2]);   // lo*hi
        }
        __syncthreads();   // all reads of buf done before refill
        if (it + 2 < NIT) stage(it + 2, buf);
    }

    // ---- epilogue: exp, fp16 v, fused row/col reductions ----
    int g = l >> 2, t2 = (l & 3)*2;
    float rsum[8], rmaxv[8]; int rargm[8];
    float csum[8], cmaxv[8];
    #pragma unroll
    for (int i = 0; i < 8; i++) { rsum[i]=0.f; rmaxv[i]=0.f; rargm[i]=0; csum[i]=0.f; cmaxv[i]=0.f; }

    #pragma unroll
    for (int fi = 0; fi < 4; fi++) {
        int r0 = n0 + wr*64 + fi*16 + g;
        #pragma unroll
        for (int fj = 0; fj < 4; fj++) {
            int c = m0 + wc*32 + fj*8 + t2;
            float* p = acc[fi][fj];
            #pragma unroll
            for (int hh = 0; hh < 2; hh++) {
                int r = r0 + hh*8;
                int ridx = fi*2 + hh;
                float e0 = __expf(p[hh*2 + 0]);
                float e1 = __expf(p[hh*2 + 1]);
                size_t o = (size_t)r*MM + c;
                __half2 hv; hv.x = __float2half_rn(e0); hv.y = __float2half_rn(e1);
                *(__half2*)(g_vhi + o) = hv;
                rsum[ridx] += e0 + e1;
                if (e0 > rmaxv[ridx]) { rmaxv[ridx] = e0; rargm[ridx] = c; }
                if (e1 > rmaxv[ridx]) { rmaxv[ridx] = e1; rargm[ridx] = c + 1; }
                int cidx = fj*2;
                csum[cidx]   += e0; cmaxv[cidx]   = fmaxf(cmaxv[cidx],   e0);
                csum[cidx+1] += e1; cmaxv[cidx+1] = fmaxf(cmaxv[cidx+1], e1);
            }
        }
    }
    // row reduce across lanes sharing the row (xor 1,2 within lane quad)
    #pragma unroll
    for (int o = 1; o <= 2; o <<= 1) {
        #pragma unroll
        for (int i = 0; i < 8; i++) {
            float os = __shfl_xor_sync(0xffffffffu, rsum[i], o);
            float om = __shfl_xor_sync(0xffffffffu, rmaxv[i], o);
            int   oa = __shfl_xor_sync(0xffffffffu, rargm[i], o);
            rsum[i] += os;
            if (om > rmaxv[i] || (om == rmaxv[i] && oa < rargm[i])) { rmaxv[i] = om; rargm[i] = oa; }
        }
    }
    // col reduce across lanes sharing the col (xor 4,8,16)
    #pragma unroll
    for (int o = 4; o <= 16; o <<= 1) {
        #pragma unroll
        for (int i = 0; i < 8; i++) {
            csum[i]  += __shfl_xor_sync(0xffffffffu, csum[i], o);
            cmaxv[i]  = fmaxf(cmaxv[i], __shfl_xor_sync(0xffffffffu, cmaxv[i], o));
        }
    }
    // smem merge (reuse pipeline smem)
    float* s_rs = (float*)dsm;
    float* s_rm = s_rs + 128;
    int*   s_ra = (int*)(s_rm + 128);
    float* s_cs = (float*)(s_ra + 128);
    float* s_cm = s_cs + 128;
    __syncthreads();
    for (int ws = 0; ws < 4; ws++) {          // stage over wc; wr rows disjoint
        if (wc == ws && (l & 3) == 0) {
            #pragma unroll
            for (int i = 0; i < 8; i++) {
                int r = wr*64 + (i >> 1)*16 + (i & 1)*8 + g;
                if (ws == 0) { s_rs[r] = rsum[i]; s_rm[r] = rmaxv[i]; s_ra[r] = rargm[i]; }
                else {
                    s_rs[r] += rsum[i];
                    if (rmaxv[i] > s_rm[r] || (rmaxv[i] == s_rm[r] && rargm[i] < s_ra[r])) {
                        s_rm[r] = rmaxv[i]; s_ra[r] = rargm[i];
                    }
                }
            }
        }
        __syncthreads();
    }
    for (int ws = 0; ws < 2; ws++) {          // stage over wr; wc cols disjoint
        if (wr == ws && l < 4) {
            #pragma unroll
            for (int i = 0; i < 8; i++) {
                int cl = wc*32 + (i >> 1)*8 + t2 + (i & 1);
                if (ws == 0) { s_cs[cl] = csum[i]; s_cm[cl] = cmaxv[i]; }
                else { s_cs[cl] += csum[i]; s_cm[cl] = fmaxf(s_cm[cl], cmaxv[i]); }
            }
        }
        __syncthreads();
    }
    if (tid < 128) {
        int n = n0 + tid;
        atomicAdd(&g_rowsumacc[n], s_rs[tid]);
        unsigned long long key =
            ((unsigned long long)__float_as_uint(s_rm[tid]) << 32) | (unsigned)(~(unsigned)s_ra[tid]);
        atomicMax(&g_rowkey[n], key);
        int m = m0 + tid;
        atomicAdd(&g_colsumacc[m], s_cs[tid]);
        atomicMax(&g_colmaxb[m], __float_as_uint(s_cm[tid]));
    }
}

// ---------------- finalize reductions + w[n] + similarity loss (merged fin+wsim) ----------------
__global__ void k_finw(const float* __restrict__ ent, float* __restrict__ out) {
    int n = blockIdx.x * blockDim.x + threadIdx.x;
    float local = 0.f;
    if (n < NN) {
        unsigned long long key = g_rowkey[n];
        float rmax = __uint_as_float((unsigned)(key >> 32));
        int g = (int)(~(unsigned)key);
        g_argm[n] = g;
        g_rrowsum[n] = 1.f / g_rowsumacc[n];
        float en = ent[n];
        float entmax = __uint_as_float(g_entmax_bits);
        float colmax = __uint_as_float(g_colmaxb[g]);
        g_w[n] = (rmax / colmax) * (en / entmax);
        float kn = sqrtf(g_knacc[g]);
        float cosv = logf(rmax) / fmaxf(kn, 1e-8f);   // ||qr|| == 1
        local = (1.f - cosv) * en;
    }
    if (n < MM) g_rcolsum[n] = 1.f / g_colsumacc[n];
    __shared__ float red[256];
    red[threadIdx.x] = local;
    __syncthreads();
    for (int o = 128; o > 0; o >>= 1) {
        if (threadIdx.x < o) red[threadIdx.x] += red[threadIdx.x + o];
        __syncthreads();
    }
    if (threadIdx.x == 0) atomicAdd(out + OFF_SIM, red[0]);
}

// ---------------- HMMA read GEMM (fp16, 1-term, 128x128) + fused sq/sm write ----------------
#define RBUF 10240      // 128 * 80
#define DSMEM_R (6*RBUF)   // 3 A + 3 B = 61440, ring-3

__global__ void __launch_bounds__(256, 2) k_read_mma(float* __restrict__ out) {
    extern __shared__ __align__(16) char dsm[];
    int tid = threadIdx.x, l = tid & 31, w = tid >> 5;
    int wr = w >> 2, wc = w & 3;
    int c0 = blockIdx.x * 128, n0 = blockIdx.y * 128;
    uint32_t as0 = smem_u32(dsm);
    uint32_t bs0 = as0 + 3*RBUF;

    float acc[4][4][4];
    #pragma unroll
    for (int i = 0; i < 4; i++)
        #pragma unroll
        for (int j = 0; j < 4; j++)
            #pragma unroll
            for (int k = 0; k < 4; k++) acc[i][j][k] = 0.f;

    auto stage = [&](int s, int buf) {
        #pragma unroll
        for (int t = 0; t < 2; t++) {
            int idx = tid + t*256;
            int r = idx >> 2, c = idx & 3;
            cpa16(as0 + buf*RBUF + r*80 + c*16,
                  (const char*)g_vhi + (size_t)(n0 + r)*2048 + s*64 + c*16);
            cpa16(bs0 + buf*RBUF + r*80 + c*16,
                  (const char*)g_kThi + (size_t)(c0 + r)*2048 + s*64 + c*16);
        }
        CP_COMMIT;
    };

    uint32_t a_off = (uint32_t)((l & 15)*80 + (l >> 4)*16);
    uint32_t b_off = (uint32_t)(((((l >> 4) & 1)*8) + (l & 7))*80 + ((l >> 3) & 1)*16);

    stage(0, 0); stage(1, 1);
    const int NIT = 32;               // 1024 m / 32 per stage
    for (int it = 0; it < NIT; it++) {
        int buf = it % 3;
        if (it < NIT - 1) CP_WAIT1; else CP_WAIT0;
        __syncthreads();
        if (it + 2 < NIT) stage(it + 2, (it + 2) % 3);
        #pragma unroll
        for (int h = 0; h < 2; h++) {
            uint32_t a[4][4], bfr[2][4];
            #pragma unroll
            for (int jp = 0; jp < 2; jp++)
                ldm_x4(bfr[jp], bs0 + buf*RBUF + (wc*32 + jp*16)*80 + h*32 + b_off);
            #pragma unroll
            for (int fi = 0; fi < 4; fi++)
                ldm_x4(a[fi], as0 + buf*RBUF + (wr*64 + fi*16)*80 + h*32 + a_off);
            #pragma unroll
            for (int fi = 0; fi < 4; fi++)
                #pragma unroll
                for (int fj = 0; fj < 4; fj++)
                    mma_f16(acc[fi][fj], a[fi], &bfr[fj >> 1][(fj & 1)*2]);
        }
        // fused sq/sm write: each c0-block writes its quarter of the 128 n-rows
        if (tid < 128) {
            int r = (blockIdx.x << 5) + (tid >> 2);
            int c = tid & 3;
            const __half2* hp = (const __half2*)(dsm + buf*RBUF + r*80 + c*16);
            int n = n0 + r;
            int m = it*32 + c*8;
            float rr = g_rrowsum[n];
            float4 rc0 = *(const float4*)(g_rcolsum + m);
            float4 rc1 = *(const float4*)(g_rcolsum + m + 4);
            float vv[8];
            #pragma unroll
            for (int j = 0; j < 4; j++) {
                float2 hf = __half22float2(hp[j]);
                vv[j*2]   = hf.x;
                vv[j*2+1] = hf.y;
            }
            size_t o = (size_t)n*MM + m;
            float4 sq0 = make_float4(vv[0]*rc0.x, vv[1]*rc0.y, vv[2]*rc0.z, vv[3]*rc0.w);
            float4 sq1 = make_float4(vv[4]*rc1.x, vv[5]*rc1.y, vv[6]*rc1.z, vv[7]*rc1.w);
            *(float4*)(out + OFF_SQ + o)     = sq0;
            *(float4*)(out + OFF_SQ + o + 4) = sq1;
            float4 sm0 = make_float4(vv[0]*rr, vv[1]*rr, vv[2]*rr, vv[3]*rr);
            float4 sm1 = make_float4(vv[4]*rr, vv[5]*rr, vv[6]*rr, vv[7]*rr);
            *(float4*)(out + OFF_SM + o)     = sm0;
            *(float4*)(out + OFF_SM + o + 4) = sm1;
        }
    }

    // epilogue: scale by rrowsum, write BCHW channels [C, 2C)
    int g = l >> 2, t2 = (l & 3)*2;
    int b = n0 >> 10;
    int hwb = n0 & 1023;
    float* obase = out + (size_t)b*UQ_STRIDE;
    #pragma unroll
    for (int fi = 0; fi < 4; fi++) {
        int rl0 = wr*64 + fi*16 + g;
        float rs0 = g_rrowsum[n0 + rl0];
        float rs1 = g_rrowsum[n0 + rl0 + 8];
        #pragma unroll
        for (int fj = 0; fj < 4; fj++) {
            int c = c0 + wc*32 + fj*8 + t2;
            float* p = acc[fi][fj];
            size_t a0 = (size_t)(CC + c)*HWDIM + hwb + rl0;
            obase[a0]              = p[0] * rs0;
            obase[a0 + HWDIM]      = p[1] * rs0;
            obase[a0 + 8]          = p[2] * rs1;
            obase[a0 + HWDIM + 8]  = p[3] * rs1;
        }
    }
}

// ---------------- HMMA gram GEMM (fp16, 2-term): diversity(updated_memory) ----------------
#define GBUF 10240      // 128 rows * 80B
#define DSMEM_G (8*GBUF)

__global__ void __launch_bounds__(256, 2) k_gram_mma(float* __restrict__ out) {
    extern __shared__ __align__(16) char dsm[];
    __shared__ float red[256];
    int tid = threadIdx.x, l = tid & 31, w = tid >> 5;
    int wr = w >> 2, wc = w & 3;
    int j0 = blockIdx.x * 128, i0 = blockIdx.y * 128;
    const __half* Ap[2] = {g_uhi, g_ulo};
    uint32_t as0 = smem_u32(dsm);
    uint32_t bs0 = as0 + 4*GBUF;

    float acc[4][4][4];
    #pragma unroll
    for (int i = 0; i < 4; i++)
        #pragma unroll
        for (int j = 0; j < 4; j++)
            #pragma unroll
            for (int k = 0; k < 4; k++) acc[i][j][k] = 0.f;

    int row2 = tid >> 2, ch = tid & 3;
    auto stage = [&](int it, int buf) {
        int seg = it >> 4;
        int k0b = (it & 15) * 64;
        const char* Ab = (const char*)Ap[seg] + (size_t)i0*1024 + k0b;
        const char* Bb = (const char*)g_uhi + (size_t)j0*1024 + k0b;
        #pragma unroll
        for (int t = 0; t < 2; t++) {
            int r = row2 + t*64;
            cpa16(as0 + buf*GBUF + r*80 + ch*16, Ab + (size_t)r*1024 + ch*16);
            cpa16(bs0 + buf*GBUF + r*80 + ch*16, Bb + (size_t)r*1024 + ch*16);
        }
        CP_COMMIT;
    };

    uint32_t a_off = (uint32_t)((l & 15)*80 + (l >> 4)*16);
    uint32_t b_off = (uint32_t)(((((l >> 4) & 1)*8) + (l & 7))*80 + ((l >> 3) & 1)*16);

    stage(0, 0); stage(1, 1);
    const int NIT = 32;
    for (int it = 0; it < NIT; it++) {
        int buf = it & 3;
        if (it < NIT - 1) CP_WAIT1; else CP_WAIT0;
        __syncthreads();
        if (it + 2 < NIT) stage(it + 2, (it + 2) & 3);
        #pragma unroll
        for (int h = 0; h < 2; h++) {
            uint32_t a[4][4];
            #pragma unroll
            for (int fi = 0; fi < 4; fi++)
                ldm_x4(a[fi], as0 + buf*GBUF + (wr*64 + fi*16)*80 + h*32 + a_off);
            uint32_t bfr[2][4];
            #pragma unroll
            for (int jp = 0; jp < 2; jp++)
                ldm_x4(bfr[jp], bs0 + buf*GBUF + (wc*32 + jp*16)*80 + h*32 + b_off);
            #pragma unroll
            for (int fi = 0; fi < 4; fi++)
                #pragma unroll
                for (int fj = 0; fj < 4; fj++)
                    mma_f16(acc[fi][fj], a[fi], &bfr[fj >> 1][(fj & 1)*2]);
        }
    }

    int g = l >> 2, t2 = (l & 3)*2;
    float local = 0.f;
    #pragma unroll
    for (int fi = 0; fi < 4; fi++) {
        int r0 = i0 + wr*64 + fi*16 + g;
        #pragma unroll
        for (int fj = 0; fj < 4; fj++) {
            int c = j0 + wc*32 + fj*8 + t2;
            float* p = acc[fi][fj];
            if (r0 != c)         local += p[0]*p[0];
            if (r0 != c + 1)     local += p[1]*p[1];
            if (r0 + 8 != c)     local += p[2]*p[2];
            if (r0 + 8 != c + 1) local += p[3]*p[3];
        }
    }
    red[tid] = local;
    __syncthreads();
    for (int o = 128; o > 0; o >>= 1) {
        if (tid < o) red[tid] += red[tid + o];
        __syncthreads();
    }
    if (tid == 0) atomicAdd(out + OFF_DIV, red[0] * (1.f / (float)(MM*MM - MM)));
}

// ---------------- segment-sum: qupd[g[n], c] += w[n]*qr[n,c] ----------------
__global__ void k_segsum(const float* __restrict__ out) {
    int idx = blockIdx.x * blockDim.x + threadIdx.x;
    if (idx >= BB*CC*HWDIM) return;
    int b = idx >> 19;
    int rem = idx & ((CC*HWDIM) - 1);
    int c = rem >> 10;
    int hw = idx & 1023;
    int n = (b << 10) | hw;
    float val = out[(size_t)b*UQ_STRIDE + rem];           // qr in BCHW layout
    atomicAdd(&g_qupd[(size_t)g_argm[n]*CC + c], g_w[n] * val);
}

// ---------------- updated memory: l2norm(qupd + keys), emit fp32 + fp16 split; re-zero qupd ----------------
__global__ void k_umem(const float* __restrict__ keys, float* __restrict__ out) {
    int m = blockIdx.x;
    int t = threadIdx.x;   // 128
    float vals[4]; float s = 0.f;
    #pragma unroll
    for (int i = 0; i < 4; i++) {
        int c = t + i*128;
        vals[i] = g_qupd[(size_t)m*CC + c] + keys[(size_t)m*CC + c];
        g_qupd[(size_t)m*CC + c] = 0.f;   // deferred zero for next graph replay
        s += vals[i]*vals[i];
    }
    for (int o = 16; o > 0; o >>= 1) s += __shfl_down_sync(0xffffffffu, s, o);
    __shared__ float red[4]; __shared__ float srn;
    if ((t & 31) == 0) red[t >> 5] = s;
    __syncthreads();
    if (t == 0) srn = 1.f / fmaxf(sqrtf(red[0]+red[1]+red[2]+red[3]), 1e-12f);
    __syncthreads();
    float rn = srn;
    #pragma unroll
    for (int i = 0; i < 4; i++) {
        int c = t + i*128;
        float u = vals[i] * rn;
        out[OFF_UMEM + (size_t)m*CC + c] = u;
        __half hi = __float2half_rn(u);
        g_uhi[(size_t)m*CC + c] = hi;
        g_ulo[(size_t)m*CC + c] = __float2half_rn(u - __half2float(hi));
    }
}

// ---------------- launch ----------------
extern "C" void kernel_launch(void* const* d_in, const int* in_sizes, int n_in,
                              void* d_out, int out_size) {
    const float* q    = (const float*)d_in[0];
    const float* keys = (const float*)d_in[1];
    const float* ent  = (const float*)d_in[2];
    float* out = (float*)d_out;

    cudaFuncSetAttribute(k_qnorm,     cudaFuncAttributeMaxDynamicSharedMemorySize, QSMEM);
    cudaFuncSetAttribute(k_score_mma, cudaFuncAttributeMaxDynamicSharedMemorySize, DSMEM_S);
    cudaFuncSetAttribute(k_read_mma,  cudaFuncAttributeMaxDynamicSharedMemorySize, DSMEM_R);
    cudaFuncSetAttribute(k_gram_mma,  cudaFuncAttributeMaxDynamicSharedMemorySize, DSMEM_G);

    k_init<<<NN/256, 256>>>(ent, out);
    k_keys<<<dim3(MM/32, CC/32), dim3(32, 8)>>>(keys);
    k_qnorm<<<dim3(HWDIM/32, BB), 256, QSMEM>>>(q, out);
    k_score_mma<<<dim3(MM/128, NN/128), 256, DSMEM_S>>>();
    k_finw<<<NN/256, 256>>>(ent, out);
    k_segsum<<<(BB*CC*HWDIM)/256, 256>>>(out);
    k_umem<<<MM, 128>>>(keys, out);
    k_gram_mma<<<dim3(MM/128, MM/128), 256, DSMEM_G>>>(out);
    k_read_mma<<<dim3(CC/128, NN/128), 256, DSMEM_R>>>(out);
}

// round 16
// speedup vs baseline: 1.5679x; 1.0439x over previous
#include <cuda_runtime.h>
#include <cuda_bf16.h>
#include <cuda_fp16.h>
#include <math.h>
#include <stdint.h>

#define BB 16
#define CC 512
#define HWDIM 1024
#define NN 16384            // B*H*W
#define MM 1024
#define UQ_STRIDE (2*CC*HWDIM)          // per-batch stride of updated_query = 1048576

// output offsets (floats)
#define OFF_UQ   ((size_t)0)
#define OFF_UMEM ((size_t)BB*UQ_STRIDE)                  // 16777216
#define OFF_SQ   (OFF_UMEM + (size_t)MM*CC)              // 17301504
#define OFF_SM   (OFF_SQ + (size_t)NN*MM)                // 34078720
#define OFF_DIV  (OFF_SM + (size_t)NN*MM)                // 50855936
#define OFF_SIM  (OFF_DIV + 1)

// ---------------- scratch (static device globals; no runtime alloc) ----------------
__device__ float g_rrowsum[NN];
__device__ int   g_argm[NN];
__device__ float g_w[NN];
__device__ float g_rcolsum[MM];
__device__ float g_knacc[MM];
__device__ float g_qupd[MM*CC];       // zero-init at load; re-zeroed by k_umem each run
__device__ unsigned g_entmax_bits;
// atomic merge targets for fused score reductions
__device__ unsigned long long g_rowkey[NN];   // (float_bits(max) << 32) | ~argmax
__device__ float g_rowsumacc[NN];
__device__ unsigned g_colmaxb[MM];
__device__ float g_colsumacc[MM];
// bf16 split operands (score GEMM, 3-term)
__device__ __nv_bfloat16 g_qhi[(size_t)NN*CC];   // qr [N][C] K-major
__device__ __nv_bfloat16 g_qlo[(size_t)NN*CC];
__device__ __nv_bfloat16 g_khi[(size_t)MM*CC];   // keys [M][C]
__device__ __nv_bfloat16 g_klo[(size_t)MM*CC];
// fp16 operands (read/gram GEMMs)
__device__ __half g_kThi[(size_t)CC*MM];         // fp16(keys^T) [C][M]
__device__ __half g_vhi[(size_t)NN*MM];          // fp16(v) [N][M]
__device__ __half g_uhi[(size_t)MM*CC];          // updated_memory split
__device__ __half g_ulo[(size_t)MM*CC];

// ---------------- PTX helpers (base sm_103-legal only) ----------------
__device__ __forceinline__ uint32_t smem_u32(const void* p) {
    uint32_t a;
    asm("{ .reg .u64 t; cvta.to.shared.u64 t, %1; cvt.u32.u64 %0, t; }" : "=r"(a) : "l"(p));
    return a;
}
__device__ __forceinline__ void ldm_x4(uint32_t* r, uint32_t a) {
    asm volatile("ldmatrix.sync.aligned.m8n8.x4.shared.b16 {%0,%1,%2,%3}, [%4];"
        : "=r"(r[0]), "=r"(r[1]), "=r"(r[2]), "=r"(r[3]) : "r"(a));
}
__device__ __forceinline__ void mma_bf16(float* c, const uint32_t* a, const uint32_t* b) {
    asm volatile("mma.sync.aligned.m16n8k16.row.col.f32.bf16.bf16.f32 "
        "{%0,%1,%2,%3}, {%4,%5,%6,%7}, {%8,%9}, {%0,%1,%2,%3};"
        : "+f"(c[0]), "+f"(c[1]), "+f"(c[2]), "+f"(c[3])
        : "r"(a[0]), "r"(a[1]), "r"(a[2]), "r"(a[3]), "r"(b[0]), "r"(b[1]));
}
__device__ __forceinline__ void mma_f16(float* c, const uint32_t* a, const uint32_t* b) {
    asm volatile("mma.sync.aligned.m16n8k16.row.col.f32.f16.f16.f32 "
        "{%0,%1,%2,%3}, {%4,%5,%6,%7}, {%8,%9}, {%0,%1,%2,%3};"
        : "+f"(c[0]), "+f"(c[1]), "+f"(c[2]), "+f"(c[3])
        : "r"(a[0]), "r"(a[1]), "r"(a[2]), "r"(a[3]), "r"(b[0]), "r"(b[1]));
}
__device__ __forceinline__ void cpa16(uint32_t dst, const void* src) {
    asm volatile("cp.async.ca.shared.global [%0], [%1], 16;" :: "r"(dst), "l"(src));
}
#define CP_COMMIT asm volatile("cp.async.commit_group;" ::: "memory")
#define CP_WAIT1  asm volatile("cp.async.wait_group 1;" ::: "memory")
#define CP_WAIT0  asm volatile("cp.async.wait_group 0;" ::: "memory")

// ---------------- small kernels ----------------

__global__ void k_init(const float* __restrict__ ent, float* __restrict__ out) {
    int i = blockIdx.x * blockDim.x + threadIdx.x;   // grid covers NN
    if (i < NN) {
        g_rowkey[i] = 0ull;
        g_rowsumacc[i] = 0.f;
        atomicMax(&g_entmax_bits, __float_as_uint(ent[i])); // entropy > 0
    }
    if (i < MM) {
        g_colmaxb[i] = 0u;
        g_colsumacc[i] = 0.f;
        g_knacc[i] = 0.f;
    }
    if (i == 0) {
        out[OFF_DIV] = 0.f;
        out[OFF_SIM] = 0.f;
    }
}

// keys -> bf16 hi/lo split [M][C], fp16(keys^T) [C][M], AND per-row norm partials
__global__ void k_keys(const float* __restrict__ keys) {
    __shared__ float t[32][33];
    int m0 = blockIdx.x * 32, c0 = blockIdx.y * 32;
    int tx = threadIdx.x, ty = threadIdx.y;  // 32 x 8; warp == fixed ty
    #pragma unroll
    for (int i = 0; i < 4; i++) {
        int row = ty + i*8;
        size_t o = (size_t)(m0 + row)*CC + c0 + tx;
        float v = keys[o];
        t[row][tx] = v;
        __nv_bfloat16 hi = __float2bfloat16(v);
        g_khi[o] = hi;
        g_klo[o] = __float2bfloat16(v - __bfloat162float(hi));
        float s = v*v;
        #pragma unroll
        for (int off = 16; off > 0; off >>= 1) s += __shfl_down_sync(0xffffffffu, s, off);
        if (tx == 0) atomicAdd(&g_knacc[m0 + row], s);
    }
    __syncthreads();
    #pragma unroll
    for (int i = 0; i < 4; i++) {
        float v = t[tx][ty + i*8];        // = keys[m0+tx][c0+ty+i*8]
        g_kThi[(size_t)(c0 + ty + i*8)*MM + m0 + tx] = __float2half_rn(v);
    }
}

// ---------------- fused: load q column-block, compute norms, write qr + bf16 split ----------------
#define QPITCH 36
#define QSMEM (512*QPITCH*4 + 128)

__global__ void __launch_bounds__(256) k_qnorm(const float* __restrict__ q, float* __restrict__ out) {
    extern __shared__ float qs[];          // [512][QPITCH] + rn[32]
    float* rn = qs + 512*QPITCH;
    int b = blockIdx.y;
    int hw0 = blockIdx.x * 32;
    int tid = threadIdx.x;
    int col = tid & 31, r0 = tid >> 5;     // 8 row-groups
    const float* src = q + (size_t)b*CC*HWDIM + hw0;
    #pragma unroll 8
    for (int i = 0; i < 64; i++) {
        int row = r0 + i*8;
        qs[row*QPITCH + col] = src[(size_t)row*HWDIM + col];
    }
    __syncthreads();
    // norms: 8 warps x 4 hw; 8 lanes per hw (conflict-free: bank = 4cb + hwl)
    int w = tid >> 5, l = tid & 31;
    {
        int hwl = w*4 + (l >> 3);
        int cb = l & 7;
        float s = 0.f;
        #pragma unroll 8
        for (int k = 0; k < 64; k++) {
            float v = qs[(cb + k*8)*QPITCH + hwl];
            s += v*v;
        }
        s += __shfl_xor_sync(0xffffffffu, s, 1);
        s += __shfl_xor_sync(0xffffffffu, s, 2);
        s += __shfl_xor_sync(0xffffffffu, s, 4);
        if (cb == 0) rn[hwl] = 1.f / fmaxf(sqrtf(s), 1e-12f);
    }
    __syncthreads();
    // write fp32 qr (BCHW layout)
    float* dst = out + (size_t)b*UQ_STRIDE + hw0;
    float rcol = rn[col];
    #pragma unroll 8
    for (int i = 0; i < 64; i++) {
        int row = r0 + i*8;
        dst[(size_t)row*HWDIM + col] = qs[row*QPITCH + col] * rcol;
    }
    // transposed bf16 hi/lo [n][c]: 8 lanes over c x 4 hw per warp (conflict-free)
    {
        int hwl = w*4 + (l >> 3);
        int n = (b << 10) | (hw0 + hwl);
        float rr = rn[hwl];
        #pragma unroll 4
        for (int cb = 0; cb < 64; cb++) {
            int c = cb*8 + (l & 7);
            float v = qs[c*QPITCH + hwl] * rr;
            __nv_bfloat16 hi = __float2bfloat16(v);
            g_qhi[(size_t)n*CC + c] = hi;
            g_qlo[(size_t)n*CC + c] = __float2bfloat16(v - __bfloat162float(hi));
        }
    }
}

// ---------------- HMMA score GEMM: co-staged bf16 hi/lo, ring-2, prefetch AFTER consume ----------------
// A/B buffer row: [hi 64B | lo 64B | pad 16B] = 144B
#define SBUF 18432      // 128 * 144
#define DSMEM_S (4*SBUF)  // 2 A + 2 B = 73728

__global__ void __launch_bounds__(256, 2) k_score_mma() {
    extern __shared__ __align__(16) char dsm[];
    int tid = threadIdx.x, l = tid & 31, w = tid >> 5;
    int wr = w >> 2, wc = w & 3;
    int m0 = blockIdx.x * 128, n0 = blockIdx.y * 128;
    uint32_t as0 = smem_u32(dsm);
    uint32_t bs0 = as0 + 2*SBUF;

    float acc[4][4][4];
    #pragma unroll
    for (int i = 0; i < 4; i++)
        #pragma unroll
        for (int j = 0; j < 4; j++)
            #pragma unroll
            for (int k = 0; k < 4; k++) acc[i][j][k] = 0.f;

    auto stage = [&](int s, int buf) {
        #pragma unroll
        for (int t = 0; t < 4; t++) {
            int idx = tid + t*256;
            int r = idx >> 3, c = idx & 7;
            const char* srcA = (c < 4)
                ? (const char*)g_qhi + (size_t)(n0 + r)*1024 + s*64 + c*16
                : (const char*)g_qlo + (size_t)(n0 + r)*1024 + s*64 + (c-4)*16;
            cpa16(as0 + buf*SBUF + r*144 + c*16, srcA);
            const char* srcB = (c < 4)
                ? (const char*)g_khi + (size_t)(m0 + r)*1024 + s*64 + c*16
                : (const char*)g_klo + (size_t)(m0 + r)*1024 + s*64 + (c-4)*16;
            cpa16(bs0 + buf*SBUF + r*144 + c*16, srcB);
        }
        CP_COMMIT;
    };

    uint32_t a_off = (uint32_t)((l & 15)*144 + (l >> 4)*16);
    uint32_t b_off = (uint32_t)(((((l >> 4) & 1)*8) + (l & 7))*144 + ((l >> 3) & 1)*16);

    stage(0, 0); stage(1, 1);
    const int NIT = 16;
    for (int it = 0; it < NIT; it++) {
        int buf = it & 1;
        if (it < NIT - 1) CP_WAIT1; else CP_WAIT0;
        __syncthreads();
        #pragma unroll
        for (int h = 0; h < 2; h++) {
            uint32_t afr[4][4], b0f[2][4], b1f[2][4];
            // A-hi, B-hi
            #pragma unroll
            for (int fi = 0; fi < 4; fi++)
                ldm_x4(afr[fi], as0 + buf*SBUF + (wr*64 + fi*16)*144 + h*32 + a_off);
            #pragma unroll
            for (int jp = 0; jp < 2; jp++)
                ldm_x4(b0f[jp], bs0 + buf*SBUF + (wc*32 + jp*16)*144 + h*32 + b_off);
            #pragma unroll
            for (int fi = 0; fi < 4; fi++)
                #pragma unroll
                for (int fj = 0; fj < 4; fj++)
                    mma_bf16(acc[fi][fj], afr[fi], &b0f[fj >> 1][(fj & 1)*2]);   // hi*hi
            // B-lo (A-hi still live)
            #pragma unroll
            for (int jp = 0; jp < 2; jp++)
                ldm_x4(b1f[jp], bs0 + buf*SBUF + (wc*32 + jp*16)*144 + 64 + h*32 + b_off);
            #pragma unroll
            for (int fi = 0; fi < 4; fi++)
                #pragma unroll
                for (int fj = 0; fj < 4; fj++)
                    mma_bf16(acc[fi][fj], afr[fi], &b1f[fj >> 1][(fj & 1)*2]);   // hi*lo
            // A-lo (reuse B-hi)
            #pragma unroll
            for (int fi = 0; fi < 4; fi++)
                ldm_x4(afr[fi], as0 + buf*SBUF + (wr*64 + fi*16)*144 + 64 + h*32 + a_off);
            #pragma unroll
            for (int fi = 0; fi < 4; fi++)
                #pragma unroll
                for (int fj = 0; fj < 4; fj++)
                    mma_bf16(acc[fi][fj], afr[fi], &b0f[fj >> 1][(fj & 1)*2]);   // lo*hi
        }
        __syncthreads();   // all reads of buf done before refill
        if (it + 2 < NIT) stage(it + 2, buf);
    }

    // ---- epilogue: exp, fp16 v, fused row/col reductions ----
    int g = l >> 2, t2 = (l & 3)*2;
    float rsum[8], rmaxv[8]; int rargm[8];
    float csum[8], cmaxv[8];
    #pragma unroll
    for (int i = 0; i < 8; i++) { rsum[i]=0.f; rmaxv[i]=0.f; rargm[i]=0; csum[i]=0.f; cmaxv[i]=0.f; }

    #pragma unroll
    for (int fi = 0; fi < 4; fi++) {
        int r0 = n0 + wr*64 + fi*16 + g;
        #pragma unroll
        for (int fj = 0; fj < 4; fj++) {
            int c = m0 + wc*32 + fj*8 + t2;
            float* p = acc[fi][fj];
            #pragma unroll
            for (int hh = 0; hh < 2; hh++) {
                int r = r0 + hh*8;
                int ridx = fi*2 + hh;
                float e0 = __expf(p[hh*2 + 0]);
                float e1 = __expf(p[hh*2 + 1]);
                size_t o = (size_t)r*MM + c;
                __half2 hv; hv.x = __float2half_rn(e0); hv.y = __float2half_rn(e1);
                *(__half2*)(g_vhi + o) = hv;
                rsum[ridx] += e0 + e1;
                if (e0 > rmaxv[ridx]) { rmaxv[ridx] = e0; rargm[ridx] = c; }
                if (e1 > rmaxv[ridx]) { rmaxv[ridx] = e1; rargm[ridx] = c + 1; }
                int cidx = fj*2;
                csum[cidx]   += e0; cmaxv[cidx]   = fmaxf(cmaxv[cidx],   e0);
                csum[cidx+1] += e1; cmaxv[cidx+1] = fmaxf(cmaxv[cidx+1], e1);
            }
        }
    }
    // row reduce across lanes sharing the row (xor 1,2 within lane quad)
    #pragma unroll
    for (int o = 1; o <= 2; o <<= 1) {
        #pragma unroll
        for (int i = 0; i < 8; i++) {
            float os = __shfl_xor_sync(0xffffffffu, rsum[i], o);
            float om = __shfl_xor_sync(0xffffffffu, rmaxv[i], o);
            int   oa = __shfl_xor_sync(0xffffffffu, rargm[i], o);
            rsum[i] += os;
            if (om > rmaxv[i] || (om == rmaxv[i] && oa < rargm[i])) { rmaxv[i] = om; rargm[i] = oa; }
        }
    }
    // col reduce across lanes sharing the col (xor 4,8,16)
    #pragma unroll
    for (int o = 4; o <= 16; o <<= 1) {
        #pragma unroll
        for (int i = 0; i < 8; i++) {
            csum[i]  += __shfl_xor_sync(0xffffffffu, csum[i], o);
            cmaxv[i]  = fmaxf(cmaxv[i], __shfl_xor_sync(0xffffffffu, cmaxv[i], o));
        }
    }
    // smem merge (reuse pipeline smem)
    float* s_rs = (float*)dsm;
    float* s_rm = s_rs + 128;
    int*   s_ra = (int*)(s_rm + 128);
    float* s_cs = (float*)(s_ra + 128);
    float* s_cm = s_cs + 128;
    __syncthreads();
    for (int ws = 0; ws < 4; ws++) {          // stage over wc; wr rows disjoint
        if (wc == ws && (l & 3) == 0) {
            #pragma unroll
            for (int i = 0; i < 8; i++) {
                int r = wr*64 + (i >> 1)*16 + (i & 1)*8 + g;
                if (ws == 0) { s_rs[r] = rsum[i]; s_rm[r] = rmaxv[i]; s_ra[r] = rargm[i]; }
                else {
                    s_rs[r] += rsum[i];
                    if (rmaxv[i] > s_rm[r] || (rmaxv[i] == s_rm[r] && rargm[i] < s_ra[r])) {
                        s_rm[r] = rmaxv[i]; s_ra[r] = rargm[i];
                    }
                }
            }
        }
        __syncthreads();
    }
    for (int ws = 0; ws < 2; ws++) {          // stage over wr; wc cols disjoint
        if (wr == ws && l < 4) {
            #pragma unroll
            for (int i = 0; i < 8; i++) {
                int cl = wc*32 + (i >> 1)*8 + t2 + (i & 1);
                if (ws == 0) { s_cs[cl] = csum[i]; s_cm[cl] = cmaxv[i]; }
                else { s_cs[cl] += csum[i]; s_cm[cl] = fmaxf(s_cm[cl], cmaxv[i]); }
            }
        }
        __syncthreads();
    }
    if (tid < 128) {
        int n = n0 + tid;
        atomicAdd(&g_rowsumacc[n], s_rs[tid]);
        unsigned long long key =
            ((unsigned long long)__float_as_uint(s_rm[tid]) << 32) | (unsigned)(~(unsigned)s_ra[tid]);
        atomicMax(&g_rowkey[n], key);
        int m = m0 + tid;
        atomicAdd(&g_colsumacc[m], s_cs[tid]);
        atomicMax(&g_colmaxb[m], __float_as_uint(s_cm[tid]));
    }
}

// ---------------- finalize reductions + w[n] + similarity loss (merged fin+wsim) ----------------
__global__ void k_finw(const float* __restrict__ ent, float* __restrict__ out) {
    int n = blockIdx.x * blockDim.x + threadIdx.x;
    float local = 0.f;
    if (n < NN) {
        unsigned long long key = g_rowkey[n];
        float rmax = __uint_as_float((unsigned)(key >> 32));
        int g = (int)(~(unsigned)key);
        g_argm[n] = g;
        g_rrowsum[n] = 1.f / g_rowsumacc[n];
        float en = ent[n];
        float entmax = __uint_as_float(g_entmax_bits);
        float colmax = __uint_as_float(g_colmaxb[g]);
        g_w[n] = (rmax / colmax) * (en / entmax);
        float kn = sqrtf(g_knacc[g]);
        float cosv = logf(rmax) / fmaxf(kn, 1e-8f);   // ||qr|| == 1
        local = (1.f - cosv) * en;
    }
    if (n < MM) g_rcolsum[n] = 1.f / g_colsumacc[n];
    __shared__ float red[256];
    red[threadIdx.x] = local;
    __syncthreads();
    for (int o = 128; o > 0; o >>= 1) {
        if (threadIdx.x < o) red[threadIdx.x] += red[threadIdx.x + o];
        __syncthreads();
    }
    if (threadIdx.x == 0) atomicAdd(out + OFF_SIM, red[0]);
}

// ---------------- HMMA read GEMM (fp16, 1-term, 128x128) + fused sq/sm write ----------------
#define RBUF 10240      // 128 * 80
#define DSMEM_R (6*RBUF)   // 3 A + 3 B = 61440, ring-3

__global__ void __launch_bounds__(256, 2) k_read_mma(float* __restrict__ out) {
    extern __shared__ __align__(16) char dsm[];
    int tid = threadIdx.x, l = tid & 31, w = tid >> 5;
    int wr = w >> 2, wc = w & 3;
    int c0 = blockIdx.x * 128, n0 = blockIdx.y * 128;
    uint32_t as0 = smem_u32(dsm);
    uint32_t bs0 = as0 + 3*RBUF;

    float acc[4][4][4];
    #pragma unroll
    for (int i = 0; i < 4; i++)
        #pragma unroll
        for (int j = 0; j < 4; j++)
            #pragma unroll
            for (int k = 0; k < 4; k++) acc[i][j][k] = 0.f;

    auto stage = [&](int s, int buf) {
        #pragma unroll
        for (int t = 0; t < 2; t++) {
            int idx = tid + t*256;
            int r = idx >> 2, c = idx & 3;
            cpa16(as0 + buf*RBUF + r*80 + c*16,
                  (const char*)g_vhi + (size_t)(n0 + r)*2048 + s*64 + c*16);
            cpa16(bs0 + buf*RBUF + r*80 + c*16,
                  (const char*)g_kThi + (size_t)(c0 + r)*2048 + s*64 + c*16);
        }
        CP_COMMIT;
    };

    uint32_t a_off = (uint32_t)((l & 15)*80 + (l >> 4)*16);
    uint32_t b_off = (uint32_t)(((((l >> 4) & 1)*8) + (l & 7))*80 + ((l >> 3) & 1)*16);

    stage(0, 0); stage(1, 1);
    const int NIT = 32;               // 1024 m / 32 per stage
    for (int it = 0; it < NIT; it++) {
        int buf = it % 3;
        if (it < NIT - 1) CP_WAIT1; else CP_WAIT0;
        __syncthreads();
        if (it + 2 < NIT) stage(it + 2, (it + 2) % 3);
        #pragma unroll
        for (int h = 0; h < 2; h++) {
            uint32_t a[4][4], bfr[2][4];
            #pragma unroll
            for (int jp = 0; jp < 2; jp++)
                ldm_x4(bfr[jp], bs0 + buf*RBUF + (wc*32 + jp*16)*80 + h*32 + b_off);
            #pragma unroll
            for (int fi = 0; fi < 4; fi++)
                ldm_x4(a[fi], as0 + buf*RBUF + (wr*64 + fi*16)*80 + h*32 + a_off);
            #pragma unroll
            for (int fi = 0; fi < 4; fi++)
                #pragma unroll
                for (int fj = 0; fj < 4; fj++)
                    mma_f16(acc[fi][fj], a[fi], &bfr[fj >> 1][(fj & 1)*2]);
        }
        // fused sq/sm write: each c0-block writes its quarter of the 128 n-rows
        if (tid < 128) {
            int r = (blockIdx.x << 5) + (tid >> 2);
            int c = tid & 3;
            const __half2* hp = (const __half2*)(dsm + buf*RBUF + r*80 + c*16);
            int n = n0 + r;
            int m = it*32 + c*8;
            float rr = g_rrowsum[n];
            float4 rc0 = *(const float4*)(g_rcolsum + m);
            float4 rc1 = *(const float4*)(g_rcolsum + m + 4);
            float vv[8];
            #pragma unroll
            for (int j = 0; j < 4; j++) {
                float2 hf = __half22float2(hp[j]);
                vv[j*2]   = hf.x;
                vv[j*2+1] = hf.y;
            }
            size_t o = (size_t)n*MM + m;
            float4 sq0 = make_float4(vv[0]*rc0.x, vv[1]*rc0.y, vv[2]*rc0.z, vv[3]*rc0.w);
            float4 sq1 = make_float4(vv[4]*rc1.x, vv[5]*rc1.y, vv[6]*rc1.z, vv[7]*rc1.w);
            *(float4*)(out + OFF_SQ + o)     = sq0;
            *(float4*)(out + OFF_SQ + o + 4) = sq1;
            float4 sm0 = make_float4(vv[0]*rr, vv[1]*rr, vv[2]*rr, vv[3]*rr);
            float4 sm1 = make_float4(vv[4]*rr, vv[5]*rr, vv[6]*rr, vv[7]*rr);
            *(float4*)(out + OFF_SM + o)     = sm0;
            *(float4*)(out + OFF_SM + o + 4) = sm1;
        }
    }

    // epilogue: scale by rrowsum, write BCHW channels [C, 2C)
    int g = l >> 2, t2 = (l & 3)*2;
    int b = n0 >> 10;
    int hwb = n0 & 1023;
    float* obase = out + (size_t)b*UQ_STRIDE;
    #pragma unroll
    for (int fi = 0; fi < 4; fi++) {
        int rl0 = wr*64 + fi*16 + g;
        float rs0 = g_rrowsum[n0 + rl0];
        float rs1 = g_rrowsum[n0 + rl0 + 8];
        #pragma unroll
        for (int fj = 0; fj < 4; fj++) {
            int c = c0 + wc*32 + fj*8 + t2;
            float* p = acc[fi][fj];
            size_t a0 = (size_t)(CC + c)*HWDIM + hwb + rl0;
            obase[a0]              = p[0] * rs0;
            obase[a0 + HWDIM]      = p[1] * rs0;
            obase[a0 + 8]          = p[2] * rs1;
            obase[a0 + HWDIM + 8]  = p[3] * rs1;
        }
    }
}

// ---------------- HMMA gram GEMM (fp16, 2-term): diversity(updated_memory) ----------------
#define GBUF 10240      // 128 rows * 80B
#define DSMEM_G (8*GBUF)

__global__ void __launch_bounds__(256, 2) k_gram_mma(float* __restrict__ out) {
    extern __shared__ __align__(16) char dsm[];
    __shared__ float red[256];
    int tid = threadIdx.x, l = tid & 31, w = tid >> 5;
    int wr = w >> 2, wc = w & 3;
    int j0 = blockIdx.x * 128, i0 = blockIdx.y * 128;
    const __half* Ap[2] = {g_uhi, g_ulo};
    uint32_t as0 = smem_u32(dsm);
    uint32_t bs0 = as0 + 4*GBUF;

    float acc[4][4][4];
    #pragma unroll
    for (int i = 0; i < 4; i++)
        #pragma unroll
        for (int j = 0; j < 4; j++)
            #pragma unroll
            for (int k = 0; k < 4; k++) acc[i][j][k] = 0.f;

    int row2 = tid >> 2, ch = tid & 3;
    auto stage = [&](int it, int buf) {
        int seg = it >> 4;
        int k0b = (it & 15) * 64;
        const char* Ab = (const char*)Ap[seg] + (size_t)i0*1024 + k0b;
        const char* Bb = (const char*)g_uhi + (size_t)j0*1024 + k0b;
        #pragma unroll
        for (int t = 0; t < 2; t++) {
            int r = row2 + t*64;
            cpa16(as0 + buf*GBUF + r*80 + ch*16, Ab + (size_t)r*1024 + ch*16);
            cpa16(bs0 + buf*GBUF + r*80 + ch*16, Bb + (size_t)r*1024 + ch*16);
        }
        CP_COMMIT;
    };

    uint32_t a_off = (uint32_t)((l & 15)*80 + (l >> 4)*16);
    uint32_t b_off = (uint32_t)(((((l >> 4) & 1)*8) + (l & 7))*80 + ((l >> 3) & 1)*16);

    stage(0, 0); stage(1, 1);
    const int NIT = 32;
    for (int it = 0; it < NIT; it++) {
        int buf = it & 3;
        if (it < NIT - 1) CP_WAIT1; else CP_WAIT0;
        __syncthreads();
        if (it + 2 < NIT) stage(it + 2, (it + 2) & 3);
        #pragma unroll
        for (int h = 0; h < 2; h++) {
            uint32_t a[4][4];
            #pragma unroll
            for (int fi = 0; fi < 4; fi++)
                ldm_x4(a[fi], as0 + buf*GBUF + (wr*64 + fi*16)*80 + h*32 + a_off);
            uint32_t bfr[2][4];
            #pragma unroll
            for (int jp = 0; jp < 2; jp++)
                ldm_x4(bfr[jp], bs0 + buf*GBUF + (wc*32 + jp*16)*80 + h*32 + b_off);
            #pragma unroll
            for (int fi = 0; fi < 4; fi++)
                #pragma unroll
                for (int fj = 0; fj < 4; fj++)
                    mma_f16(acc[fi][fj], a[fi], &bfr[fj >> 1][(fj & 1)*2]);
        }
    }

    int g = l >> 2, t2 = (l & 3)*2;
    float local = 0.f;
    #pragma unroll
    for (int fi = 0; fi < 4; fi++) {
        int r0 = i0 + wr*64 + fi*16 + g;
        #pragma unroll
        for (int fj = 0; fj < 4; fj++) {
            int c = j0 + wc*32 + fj*8 + t2;
            float* p = acc[fi][fj];
            if (r0 != c)         local += p[0]*p[0];
            if (r0 != c + 1)     local += p[1]*p[1];
            if (r0 + 8 != c)     local += p[2]*p[2];
            if (r0 + 8 != c + 1) local += p[3]*p[3];
        }
    }
    red[tid] = local;
    __syncthreads();
    for (int o = 128; o > 0; o >>= 1) {
        if (tid < o) red[tid] += red[tid + o];
        __syncthreads();
    }
    if (tid == 0) atomicAdd(out + OFF_DIV, red[0] * (1.f / (float)(MM*MM - MM)));
}

// ---------------- segment-sum: qupd[g[n], c] += w[n]*qr[n,c] ----------------
__global__ void k_segsum(const float* __restrict__ out) {
    int idx = blockIdx.x * blockDim.x + threadIdx.x;
    if (idx >= BB*CC*HWDIM) return;
    int b = idx >> 19;
    int rem = idx & ((CC*HWDIM) - 1);
    int c = rem >> 10;
    int hw = idx & 1023;
    int n = (b << 10) | hw;
    float val = out[(size_t)b*UQ_STRIDE + rem];           // qr in BCHW layout
    atomicAdd(&g_qupd[(size_t)g_argm[n]*CC + c], g_w[n] * val);
}

// ---------------- updated memory: l2norm(qupd + keys), emit fp32 + fp16 split; re-zero qupd ----------------
__global__ void k_umem(const float* __restrict__ keys, float* __restrict__ out) {
    int m = blockIdx.x;
    int t = threadIdx.x;   // 128
    float vals[4]; float s = 0.f;
    #pragma unroll
    for (int i = 0; i < 4; i++) {
        int c = t + i*128;
        vals[i] = g_qupd[(size_t)m*CC + c] + keys[(size_t)m*CC + c];
        g_qupd[(size_t)m*CC + c] = 0.f;   // deferred zero for next graph replay
        s += vals[i]*vals[i];
    }
    for (int o = 16; o > 0; o >>= 1) s += __shfl_down_sync(0xffffffffu, s, o);
    __shared__ float red[4]; __shared__ float srn;
    if ((t & 31) == 0) red[t >> 5] = s;
    __syncthreads();
    if (t == 0) srn = 1.f / fmaxf(sqrtf(red[0]+red[1]+red[2]+red[3]), 1e-12f);
    __syncthreads();
    float rn = srn;
    #pragma unroll
    for (int i = 0; i < 4; i++) {
        int c = t + i*128;
        float u = vals[i] * rn;
        out[OFF_UMEM + (size_t)m*CC + c] = u;
        __half hi = __float2half_rn(u);
        g_uhi[(size_t)m*CC + c] = hi;
        g_ulo[(size_t)m*CC + c] = __float2half_rn(u - __half2float(hi));
    }
}

// ---------------- launch ----------------
extern "C" void kernel_launch(void* const* d_in, const int* in_sizes, int n_in,
                              void* d_out, int out_size) {
    const float* q    = (const float*)d_in[0];
    const float* keys = (const float*)d_in[1];
    const float* ent  = (const float*)d_in[2];
    float* out = (float*)d_out;

    cudaFuncSetAttribute(k_qnorm,     cudaFuncAttributeMaxDynamicSharedMemorySize, QSMEM);
    cudaFuncSetAttribute(k_score_mma, cudaFuncAttributeMaxDynamicSharedMemorySize, DSMEM_S);
    cudaFuncSetAttribute(k_read_mma,  cudaFuncAttributeMaxDynamicSharedMemorySize, DSMEM_R);
    cudaFuncSetAttribute(k_gram_mma,  cudaFuncAttributeMaxDynamicSharedMemorySize, DSMEM_G);

    // serial prefix on the main (captured) stream
    k_init<<<NN/256, 256>>>(ent, out);
    k_keys<<<dim3(MM/32, CC/32), dim3(32, 8)>>>(keys);
    k_qnorm<<<dim3(HWDIM/32, BB), 256, QSMEM>>>(q, out);
    k_score_mma<<<dim3(MM/128, NN/128), 256, DSMEM_S>>>();
    k_finw<<<NN/256, 256>>>(ent, out);

    // fork: read GEMM (independent of update chain) on a side stream
    cudaStream_t s2;
    cudaStreamCreateWithFlags(&s2, cudaStreamNonBlocking);
    cudaEvent_t eFork, eJoin;
    cudaEventCreateWithFlags(&eFork, cudaEventDisableTiming);
    cudaEventCreateWithFlags(&eJoin, cudaEventDisableTiming);

    cudaEventRecord(eFork, 0);
    cudaStreamWaitEvent(s2, eFork, 0);
    k_read_mma<<<dim3(CC/128, NN/128), 256, DSMEM_R, s2>>>(out);
    cudaEventRecord(eJoin, s2);

    // update chain on main stream, concurrent with the read GEMM
    k_segsum<<<(BB*CC*HWDIM)/256, 256>>>(out);
    k_umem<<<MM, 128>>>(keys, out);
    k_gram_mma<<<dim3(MM/128, MM/128), 256, DSMEM_G>>>(out);

    // join
    cudaStreamWaitEvent(0, eJoin, 0);

    cudaEventDestroy(eFork);
    cudaEventDestroy(eJoin);
    // NOTE: s2 is intentionally NOT destroyed here — destroying a stream that
    // participated in an ongoing capture invalidates the capture. The handful
    // of streams created across the harness's few kernel_launch calls is a
    // bounded host-side resource, not device memory.
}